// round 1
// baseline (speedup 1.0000x reference)
#include <cuda_runtime.h>
#include <cstdint>

#define NN 8192
#define HH 256
#define TOPK 16
#define NSEC 11
#define NEG_SLOPE 0.2f

// ---------------- device scratch (no allocations allowed) ----------------
__device__ float g_v1[HH];
__device__ float g_v2[HH];
__device__ float g_s1[NN];
__device__ float g_s2[NN];
__device__ int   g_top_idx[NSEC][TOPK];
__device__ float g_top_s2[NSEC][TOPK];
__device__ int   g_top_cnt[NSEC];
__device__ int   g_mask_mode;   // 0 = uint8, 1 = int32, 2 = float32

// ---------------- helpers ----------------
__device__ __forceinline__ bool is_active(const void* am, int i, int mode) {
    if (mode == 0) return ((const unsigned char*)am)[i] != 0;
    if (mode == 1) return ((const int*)am)[i] != 0;
    return ((const float*)am)[i] != 0.0f;
}

// Detect active_mask storage layout by scanning the first NN BYTES (safe in
// every candidate layout: u8 buffer is exactly NN bytes, 4-byte layouts are
// 4*NN bytes). Deterministic.
__global__ void k_detect(const unsigned char* am) {
    __shared__ int s_gt1, s_nz_off, s_nz_al;
    if (threadIdx.x == 0) { s_gt1 = 0; s_nz_off = 0; s_nz_al = 0; }
    __syncthreads();
    int l_gt1 = 0, l_off = 0, l_al = 0;
    for (int p = threadIdx.x; p < NN; p += blockDim.x) {
        unsigned char b = am[p];
        if (b > 1) l_gt1 = 1;
        if (b != 0) { if (p & 3) l_off = 1; else l_al = 1; }
    }
    if (l_gt1) atomicOr(&s_gt1, 1);
    if (l_off) atomicOr(&s_nz_off, 1);
    if (l_al)  atomicOr(&s_nz_al, 1);
    __syncthreads();
    if (threadIdx.x == 0) {
        int mode;
        if (s_gt1) {
            // bytes outside {0,1}: either float32 (nonzero only at p%4==2,3)
            // or u8 with non-canonical truth values (nonzero at aligned too)
            mode = s_nz_al ? 0 : 2;
        } else {
            // all bytes in {0,1}
            mode = s_nz_off ? 0 : 1;
        }
        g_mask_mode = mode;
    }
}

// v1 = W^T a[:H], v2 = W^T a[H:].  One block, H threads; iteration k reads a
// contiguous row W[k, 0..H) -> fully coalesced.
__global__ void k_proj(const float* __restrict__ W, const float* __restrict__ a) {
    int c = threadIdx.x;
    float acc1 = 0.f, acc2 = 0.f;
#pragma unroll 8
    for (int k = 0; k < HH; k++) {
        float w = W[k * HH + c];
        acc1 = fmaf(w, __ldg(&a[k]),      acc1);
        acc2 = fmaf(w, __ldg(&a[HH + k]), acc2);
    }
    g_v1[c] = acc1;
    g_v2[c] = acc2;
}

// s1 = E @ v1, s2 = E @ v2.  One warp per row; 8 warps/block.
__global__ void k_scores(const float* __restrict__ E) {
    __shared__ float sv1[HH], sv2[HH];
    int t = threadIdx.x;               // 256 threads == HH
    sv1[t] = g_v1[t];
    sv2[t] = g_v2[t];
    __syncthreads();
    int warp = t >> 5, lane = t & 31;
    int row = blockIdx.x * 8 + warp;
    const float* e = E + (size_t)row * HH;
    float a1 = 0.f, a2 = 0.f;
#pragma unroll
    for (int k = lane; k < HH; k += 32) {
        float x = e[k];
        a1 = fmaf(x, sv1[k], a1);
        a2 = fmaf(x, sv2[k], a2);
    }
#pragma unroll
    for (int o = 16; o; o >>= 1) {
        a1 += __shfl_xor_sync(0xFFFFFFFFu, a1, o);
        a2 += __shfl_xor_sync(0xFFFFFFFFu, a2, o);
    }
    if (lane == 0) { g_s1[row] = a1; g_s2[row] = a2; }
}

// Per-sector top-16 of s2 over {j : active[j] && sector[j]==sec}.
// Key = (monotone_u32(s2) << 32) | ~j  -> max-order == (s2 desc, idx asc),
// matching jax.lax.top_k tie-breaking. One block of 1024 threads per sector.
__global__ void k_topk(const int* __restrict__ sector, const void* __restrict__ am) {
    int sec = blockIdx.x;
    int tid = threadIdx.x;             // 1024 threads
    int mode = g_mask_mode;

    unsigned long long cand[8];
    int cn = 0;
#pragma unroll
    for (int t = 0; t < 8; t++) {
        int i = tid + t * 1024;
        if (sector[i] == sec && is_active(am, i, mode)) {
            unsigned u = __float_as_uint(g_s2[i]);
            u = (u & 0x80000000u) ? ~u : (u | 0x80000000u);
            cand[cn++] = ((unsigned long long)u << 32) | (unsigned)(~i);
        }
    }
    // sort local candidates descending (<=8, unique keys)
    for (int a = 1; a < cn; a++) {
        unsigned long long v = cand[a];
        int b = a;
        while (b > 0 && cand[b - 1] < v) { cand[b] = cand[b - 1]; b--; }
        cand[b] = v;
    }

    __shared__ unsigned long long red[1024];
    int head = 0;
    int filled = 0;
    for (int k = 0; k < TOPK; k++) {
        unsigned long long my = (head < cn) ? cand[head] : 0ull;
        red[tid] = my;
        __syncthreads();
        for (int off = 512; off; off >>= 1) {
            if (tid < off) {
                unsigned long long o = red[tid + off];
                if (o > red[tid]) red[tid] = o;
            }
            __syncthreads();
        }
        unsigned long long win = red[0];
        __syncthreads();
        if (win == 0ull) break;        // members exhausted (uniform exit)
        if (my == win) head++;         // unique winner pops its head
        if (tid == 0) {
            int idx = (int)(~(unsigned)(win & 0xFFFFFFFFull));
            g_top_idx[sec][k] = idx;
            g_top_s2[sec][k]  = g_s2[idx];
        }
        filled = k + 1;
    }
    if (tid == 0) {
        g_top_cnt[sec] = filled;
        // Fill remaining slots with the smallest NON-member indices (these are
        // the -inf ties; jax top_k picks them in ascending index order).
        int k = filled, j = 0;
        while (k < TOPK && j < NN) {
            bool mem = (sector[j] == sec) && is_active(am, j, mode);
            if (!mem) { g_top_idx[sec][k] = j; g_top_s2[sec][k] = 0.f; k++; }
            j++;
        }
        while (k < TOPK) { g_top_idx[sec][k] = 0; g_top_s2[sec][k] = 0.f; k++; }
    }
}

// Emit outputs: [edge_weight (N*16) | topk_indices (N*16) | valid (N*16)],
// all as the output dtype (float32). One thread per (row, k).
__global__ void k_out(const int* __restrict__ sector, const void* __restrict__ am,
                      float* __restrict__ out, int out_size) {
    int gid = blockIdx.x * blockDim.x + threadIdx.x;
    if (gid >= NN * TOPK) return;
    int row = gid >> 4;
    int k   = gid & 15;
    int mode = g_mask_mode;

    float w, val;
    int idx;
    if (!is_active(am, row, mode)) {
        // whole row is -inf: top_k returns indices 0..15, invalid, weight 0
        w = 0.f; idx = k; val = 0.f;
    } else {
        int s   = sector[row];
        int cnt = g_top_cnt[s];
        idx = g_top_idx[s][k];
        if (k < cnt) {
            float x = g_s1[row] + g_top_s2[s][k];
            w   = (x >= 0.f) ? x : NEG_SLOPE * x;   // leaky_relu, TEMPERATURE=1
            val = 1.f;
        } else {
            w = 0.f; val = 0.f;
        }
    }
    const int NT = NN * TOPK;
    out[gid] = w;
    if (out_size >= 2 * NT) out[NT + gid]     = (float)idx;
    if (out_size >= 3 * NT) out[2 * NT + gid] = val;
}

extern "C" void kernel_launch(void* const* d_in, const int* in_sizes, int n_in,
                              void* d_out, int out_size) {
    const float* E      = (const float*)d_in[0];   // embeddings [N, H]
    const float* W      = (const float*)d_in[1];   // W [H, H]
    const float* a      = (const float*)d_in[2];   // a [2H]
    const int*   sector = (const int*)d_in[3];     // sector_ids [N]
    const void*  am     = d_in[4];                 // active_mask [N], dtype detected
    float* out = (float*)d_out;

    k_detect<<<1, 256>>>((const unsigned char*)am);
    k_proj  <<<1, HH>>>(W, a);
    k_scores<<<NN / 8, 256>>>(E);
    k_topk  <<<NSEC, 1024>>>(sector, am);
    k_out   <<<(NN * TOPK + 255) / 256, 256>>>(sector, am, out, out_size);
}